// round 6
// baseline (speedup 1.0000x reference)
#include <cuda_runtime.h>

#define NPTS   1048576
#define BLK    128

// tanh via fast exp: accurate to ~1e-6, far inside the 1e-3 budget.
__device__ __forceinline__ float fast_tanh(float v) {
    float e = __expf(2.0f * v);
    return 1.0f - __fdividef(2.0f, e + 1.0f);
}

__global__ __launch_bounds__(BLK)
void pfnn_kernel(const float* __restrict__ x,
                 const float* __restrict__ W0, const float* __restrict__ b0,
                 const float* __restrict__ W1, const float* __restrict__ b1,
                 const float* __restrict__ W2, const float* __restrict__ b2,
                 const float* __restrict__ W3, const float* __restrict__ b3,
                 float* __restrict__ out)
{
    // Shared weight staging. W1/W2 stored TRANSPOSED: [b][j_out][k_in] so each
    // output neuron's 32 input weights are contiguous -> LDS.128.
    __shared__ float sW0[4 * 3 * 32];   // [b][d][j]
    __shared__ float sB0[4 * 32];
    __shared__ float sW1[4 * 32 * 32];  // [b][j][k]  (transposed)
    __shared__ float sB1[4 * 32];
    __shared__ float sW2[4 * 32 * 32];  // [b][j][k]  (transposed)
    __shared__ float sB2[4 * 32];
    __shared__ float sW3[4 * 32];       // [b][k]
    __shared__ float sB3[4];

    const int tid = threadIdx.x;

    for (int i = tid; i < 384; i += BLK) sW0[i] = W0[i];
    for (int i = tid; i < 128; i += BLK) {
        sB0[i] = b0[i];
        sB1[i] = b1[i];
        sB2[i] = b2[i];
        sW3[i] = W3[i];
    }
    if (tid < 4) sB3[tid] = b3[tid];
    for (int i = tid; i < 4096; i += BLK) {
        // global layout: [b][k][j], i = (b<<10) + (k<<5) + j
        int b = i >> 10;
        int r = i & 1023;
        int k = r >> 5;
        int j = r & 31;
        int t = (b << 10) + (j << 5) + k;   // transposed slot
        sW1[t] = W1[i];
        sW2[t] = W2[i];
    }
    __syncthreads();

    const int n = blockIdx.x * BLK + tid;

    const float x0 = x[3 * n + 0];
    const float x1 = x[3 * n + 1];
    const float x2 = x[3 * n + 2];

    // Branch loop kept rolled to bound code size; all inner loops fully
    // unrolled so h[]/g[] stay in registers.
    #pragma unroll 1
    for (int b = 0; b < 4; ++b) {
        const float* w0 = &sW0[b * 96];
        const float* bb0 = &sB0[b * 32];

        float h[32];
        #pragma unroll
        for (int j = 0; j < 32; ++j) {
            float a = bb0[j]
                    + x0 * w0[j]
                    + x1 * w0[32 + j]
                    + x2 * w0[64 + j];
            h[j] = fast_tanh(a);
        }

        const float4* w1 = (const float4*)&sW1[b * 1024];
        const float* bb1 = &sB1[b * 32];
        float g[32];
        #pragma unroll
        for (int j = 0; j < 32; ++j) {
            float a = bb1[j];
            #pragma unroll
            for (int kk = 0; kk < 8; ++kk) {
                float4 w = w1[j * 8 + kk];
                a += h[4 * kk + 0] * w.x;
                a += h[4 * kk + 1] * w.y;
                a += h[4 * kk + 2] * w.z;
                a += h[4 * kk + 3] * w.w;
            }
            g[j] = fast_tanh(a);
        }

        const float4* w2 = (const float4*)&sW2[b * 1024];
        const float* bb2 = &sB2[b * 32];
        #pragma unroll
        for (int j = 0; j < 32; ++j) {
            float a = bb2[j];
            #pragma unroll
            for (int kk = 0; kk < 8; ++kk) {
                float4 w = w2[j * 8 + kk];
                a += g[4 * kk + 0] * w.x;
                a += g[4 * kk + 1] * w.y;
                a += g[4 * kk + 2] * w.z;
                a += g[4 * kk + 3] * w.w;
            }
            h[j] = fast_tanh(a);
        }

        const float4* w3 = (const float4*)&sW3[b * 32];
        float a = sB3[b];
        #pragma unroll
        for (int kk = 0; kk < 8; ++kk) {
            float4 w = w3[kk];
            a += h[4 * kk + 0] * w.x;
            a += h[4 * kk + 1] * w.y;
            a += h[4 * kk + 2] * w.z;
            a += h[4 * kk + 3] * w.w;
        }

        out[n * 4 + b] = a;   // output layout [N, B]
    }
}

extern "C" void kernel_launch(void* const* d_in, const int* in_sizes, int n_in,
                              void* d_out, int out_size)
{
    const float* x  = (const float*)d_in[0];
    const float* W0 = (const float*)d_in[1];
    const float* b0 = (const float*)d_in[2];
    const float* W1 = (const float*)d_in[3];
    const float* b1 = (const float*)d_in[4];
    const float* W2 = (const float*)d_in[5];
    const float* b2 = (const float*)d_in[6];
    const float* W3 = (const float*)d_in[7];
    const float* b3 = (const float*)d_in[8];
    float* out = (float*)d_out;

    const int n = in_sizes[0] / 3;   // N points
    pfnn_kernel<<<n / BLK, BLK>>>(x, W0, b0, W1, b1, W2, b2, W3, b3, out);
}

// round 11
// speedup vs baseline: 1.0605x; 1.0605x over previous
#include <cuda_runtime.h>

#define BLK 128

// tanh via fast exp: accurate to ~1e-6, far inside the 1e-3 budget.
__device__ __forceinline__ float fast_tanh(float v) {
    float e = __expf(2.0f * v);
    return 1.0f - __fdividef(2.0f, e + 1.0f);
}

__global__ __launch_bounds__(BLK, 3)
void pfnn_kernel(const float* __restrict__ x,
                 const float* __restrict__ W0, const float* __restrict__ b0,
                 const float* __restrict__ W1, const float* __restrict__ b1,
                 const float* __restrict__ W2, const float* __restrict__ b2,
                 const float* __restrict__ W3, const float* __restrict__ b3,
                 float* __restrict__ out)
{
    // Shared weight staging. W1/W2 stored TRANSPOSED: [b][j_out][k_in] so each
    // output neuron's 32 input weights are contiguous -> LDS.128.
    __shared__ float sW0[4 * 3 * 32];   // [b][d][j]
    __shared__ float sB0[4 * 32];
    __shared__ float sW1[4 * 32 * 32];  // [b][j][k]  (transposed)
    __shared__ float sB1[4 * 32];
    __shared__ float sW2[4 * 32 * 32];  // [b][j][k]  (transposed)
    __shared__ float sB2[4 * 32];
    __shared__ float sW3[4 * 32];       // [b][k]
    __shared__ float sB3[4];

    const int tid = threadIdx.x;

    for (int i = tid; i < 384; i += BLK) sW0[i] = W0[i];
    for (int i = tid; i < 128; i += BLK) {
        sB0[i] = b0[i];
        sB1[i] = b1[i];
        sB2[i] = b2[i];
        sW3[i] = W3[i];
    }
    if (tid < 4) sB3[tid] = b3[tid];
    for (int i = tid; i < 4096; i += BLK) {
        // global layout: [b][k][j], i = (b<<10) + (k<<5) + j
        int b = i >> 10;
        int r = i & 1023;
        int k = r >> 5;
        int j = r & 31;
        int t = (b << 10) + (j << 5) + k;   // transposed slot
        sW1[t] = W1[i];
        sW2[t] = W2[i];
    }
    __syncthreads();

    // Two points per thread: every weight loaded from smem is used twice.
    const int na = blockIdx.x * (2 * BLK) + tid;   // point A
    const int nb = na + BLK;                       // point B

    const float xa0 = x[3 * na + 0];
    const float xa1 = x[3 * na + 1];
    const float xa2 = x[3 * na + 2];
    const float xb0 = x[3 * nb + 0];
    const float xb1 = x[3 * nb + 1];
    const float xb2 = x[3 * nb + 2];

    // Branch loop kept rolled to bound code size; all inner loops fully
    // unrolled so the activation arrays stay in registers.
    #pragma unroll 1
    for (int b = 0; b < 4; ++b) {
        const float* w0  = &sW0[b * 96];
        const float* bb0 = &sB0[b * 32];

        float ha[32], hb[32];
        #pragma unroll
        for (int j = 0; j < 32; ++j) {
            const float wj0 = w0[j];
            const float wj1 = w0[32 + j];
            const float wj2 = w0[64 + j];
            const float bj  = bb0[j];
            ha[j] = fast_tanh(bj + xa0 * wj0 + xa1 * wj1 + xa2 * wj2);
            hb[j] = fast_tanh(bj + xb0 * wj0 + xb1 * wj1 + xb2 * wj2);
        }

        const float4* w1  = (const float4*)&sW1[b * 1024];
        const float*  bb1 = &sB1[b * 32];
        float ga[32], gb[32];
        #pragma unroll
        for (int j = 0; j < 32; ++j) {
            float aa = bb1[j];
            float ab = aa;
            #pragma unroll
            for (int kk = 0; kk < 8; ++kk) {
                float4 w = w1[j * 8 + kk];
                aa += ha[4 * kk + 0] * w.x;  ab += hb[4 * kk + 0] * w.x;
                aa += ha[4 * kk + 1] * w.y;  ab += hb[4 * kk + 1] * w.y;
                aa += ha[4 * kk + 2] * w.z;  ab += hb[4 * kk + 2] * w.z;
                aa += ha[4 * kk + 3] * w.w;  ab += hb[4 * kk + 3] * w.w;
            }
            ga[j] = fast_tanh(aa);
            gb[j] = fast_tanh(ab);
        }

        const float4* w2  = (const float4*)&sW2[b * 1024];
        const float*  bb2 = &sB2[b * 32];
        #pragma unroll
        for (int j = 0; j < 32; ++j) {
            float aa = bb2[j];
            float ab = aa;
            #pragma unroll
            for (int kk = 0; kk < 8; ++kk) {
                float4 w = w2[j * 8 + kk];
                aa += ga[4 * kk + 0] * w.x;  ab += gb[4 * kk + 0] * w.x;
                aa += ga[4 * kk + 1] * w.y;  ab += gb[4 * kk + 1] * w.y;
                aa += ga[4 * kk + 2] * w.z;  ab += gb[4 * kk + 2] * w.z;
                aa += ga[4 * kk + 3] * w.w;  ab += gb[4 * kk + 3] * w.w;
            }
            ha[j] = fast_tanh(aa);
            hb[j] = fast_tanh(ab);
        }

        const float4* w3 = (const float4*)&sW3[b * 32];
        float oa = sB3[b];
        float ob = oa;
        #pragma unroll
        for (int kk = 0; kk < 8; ++kk) {
            float4 w = w3[kk];
            oa += ha[4 * kk + 0] * w.x;  ob += hb[4 * kk + 0] * w.x;
            oa += ha[4 * kk + 1] * w.y;  ob += hb[4 * kk + 1] * w.y;
            oa += ha[4 * kk + 2] * w.z;  ob += hb[4 * kk + 2] * w.z;
            oa += ha[4 * kk + 3] * w.w;  ob += hb[4 * kk + 3] * w.w;
        }

        out[na * 4 + b] = oa;   // output layout [N, B]
        out[nb * 4 + b] = ob;
    }
}

extern "C" void kernel_launch(void* const* d_in, const int* in_sizes, int n_in,
                              void* d_out, int out_size)
{
    const float* x  = (const float*)d_in[0];
    const float* W0 = (const float*)d_in[1];
    const float* b0 = (const float*)d_in[2];
    const float* W1 = (const float*)d_in[3];
    const float* b1 = (const float*)d_in[4];
    const float* W2 = (const float*)d_in[5];
    const float* b2 = (const float*)d_in[6];
    const float* W3 = (const float*)d_in[7];
    const float* b3 = (const float*)d_in[8];
    float* out = (float*)d_out;

    const int n = in_sizes[0] / 3;          // N points
    pfnn_kernel<<<n / (2 * BLK), BLK>>>(x, W0, b0, W1, b1, W2, b2, W3, b3, out);
}